// round 4
// baseline (speedup 1.0000x reference)
#include <cuda_runtime.h>

#define NC 19
#define HWS (512*512)
#define NPIX (16*HWS)                 // 4,194,304 pixels
#define EPSF 1e-8f
#define THREADS 256
#define NBLOCKS (NPIX/THREADS)        // 16384

__device__ float g_partial[NBLOCKS];
__device__ unsigned int g_count;      // zero-initialized; self-resetting

__global__ void __launch_bounds__(THREADS)
emloss_fused(const float* __restrict__ logits,
             const int*   __restrict__ targets,
             const float* __restrict__ cm,
             float* __restrict__ pred_out,
             float* __restrict__ out_scalar)
{
    __shared__ float s_ncm[NC*NC];
    __shared__ float s_log[NC*NC];

    const int p  = blockIdx.x * THREADS + threadIdx.x;   // pixel index
    const int b  = p / HWS;
    const int hw = p - b * HWS;
    const float* lbase = logits   + (size_t)b * NC * HWS + hw;
    float*       pbase = pred_out + (size_t)b * NC * HWS + hw;

    // Issue all 19 loads up front (MLP=19), streaming (no reuse)
    float x[NC];
    #pragma unroll
    for (int c = 0; c < NC; c++)
        x[c] = __ldcs(lbase + (size_t)c * HWS);
    const int t = targets[p];

    // Recompute 19x19 confusion-softmax tables per block — hides under load latency
    if (threadIdx.x < NC) {
        const int r = threadIdx.x;
        float row[NC];
        float m = -1e30f;
        #pragma unroll
        for (int j = 0; j < NC; j++) { row[j] = cm[r*NC + j]; m = fmaxf(m, row[j]); }
        float s = 0.f;
        #pragma unroll
        for (int j = 0; j < NC; j++) { row[j] = expf(row[j] - m); s += row[j]; }
        const float inv = 1.f / s;
        #pragma unroll
        for (int j = 0; j < NC; j++) {
            float v = row[j] * inv;
            s_ncm[r*NC + j] = v;
            s_log[r*NC + j] = logf(v + EPSF);
        }
    }
    __syncthreads();

    // Stable softmax over classes
    float m = x[0];
    #pragma unroll
    for (int c = 1; c < NC; c++) m = fmaxf(m, x[c]);
    float s = 0.f;
    #pragma unroll
    for (int c = 0; c < NC; c++) { x[c] = __expf(x[c] - m); s += x[c]; }
    const float inv = 1.f / s;

    // Single pass: store pred (streaming), accumulate ns and A
    float ns = 0.f, A = 0.f;
    #pragma unroll
    for (int c = 0; c < NC; c++) {
        const float pv = x[c] * inv;
        __stcs(pbase + (size_t)c * HWS, pv);
        const float w = s_ncm[c*NC + t];
        const float e = w * pv;
        ns += e;
        A  += e * (s_log[c*NC + t] + __logf(pv + EPSF));
    }
    float loss = A / ns;

    // Deterministic block reduction
    #pragma unroll
    for (int off = 16; off > 0; off >>= 1)
        loss += __shfl_down_sync(0xffffffffu, loss, off);

    __shared__ float s_red[THREADS/32];
    __shared__ bool  s_last;
    if ((threadIdx.x & 31) == 0) s_red[threadIdx.x >> 5] = loss;
    __syncthreads();
    if (threadIdx.x == 0) {
        float v = 0.f;
        #pragma unroll
        for (int i = 0; i < THREADS/32; i++) v += s_red[i];
        g_partial[blockIdx.x] = v;
        __threadfence();
        unsigned int prev = atomicAdd(&g_count, 1u);
        s_last = (prev == NBLOCKS - 1);
    }
    __syncthreads();

    // Last block: deterministic final reduction over all block partials
    if (s_last) {
        float sv = 0.f;
        for (int i = threadIdx.x; i < NBLOCKS; i += THREADS)
            sv += __ldcg(&g_partial[i]);                 // fixed per-thread order
        #pragma unroll
        for (int off = 16; off > 0; off >>= 1)
            sv += __shfl_down_sync(0xffffffffu, sv, off);
        if ((threadIdx.x & 31) == 0) s_red[threadIdx.x >> 5] = sv;
        __syncthreads();
        if (threadIdx.x == 0) {
            float v = 0.f;
            #pragma unroll
            for (int i = 0; i < THREADS/32; i++) v += s_red[i];
            out_scalar[0] = -v / (float)NPIX;
            g_count = 0;                                 // reset for graph replay
        }
    }
}

extern "C" void kernel_launch(void* const* d_in, const int* in_sizes, int n_in,
                              void* d_out, int out_size) {
    const float* logits  = (const float*)d_in[0];
    const int*   targets = (const int*)d_in[1];
    const float* cm      = (const float*)d_in[2];
    float* out = (float*)d_out;

    emloss_fused<<<NBLOCKS, THREADS>>>(logits, targets, cm, out, out + (out_size - 1));
}

// round 5
// speedup vs baseline: 1.0847x; 1.0847x over previous
#include <cuda_runtime.h>

#define NC 19
#define HWS (512*512)
#define NPIX (16*HWS)                 // 4,194,304 pixels
#define EPSF 1e-8f
#define THREADS 256
#define NBLOCKS (NPIX/THREADS)        // 16384

__device__ float g_ncm[NC*NC];
__device__ float g_logncm[NC*NC];
__device__ float g_partial[NBLOCKS];
__device__ unsigned int g_count;      // zero-initialized; self-resetting

// ---------------------------------------------------------------------------
// Prep: warp-per-row softmax of the 19x19 confusion matrix (19 warps).
// Each lane handles one element: 1 exp + 1 log per lane, shuffle reductions.
// ---------------------------------------------------------------------------
__global__ void prep_kernel(const float* __restrict__ cm) {
    const int w = threadIdx.x >> 5;       // row
    const int j = threadIdx.x & 31;       // col
    if (w >= NC) return;
    float v = (j < NC) ? cm[w*NC + j] : -1e30f;

    float m = v;
    #pragma unroll
    for (int off = 16; off > 0; off >>= 1)
        m = fmaxf(m, __shfl_xor_sync(0xffffffffu, m, off));

    float e = (j < NC) ? expf(v - m) : 0.f;
    float s = e;
    #pragma unroll
    for (int off = 16; off > 0; off >>= 1)
        s += __shfl_xor_sync(0xffffffffu, s, off);

    if (j < NC) {
        float p = e / s;
        g_ncm[w*NC + j]    = p;
        g_logncm[w*NC + j] = logf(p + EPSF);
    }
}

// ---------------------------------------------------------------------------
// Main: per-pixel softmax + EM loss + fused deterministic reduction
// ---------------------------------------------------------------------------
__global__ void __launch_bounds__(THREADS, 5)
emloss_main(const float* __restrict__ logits,
            const int*   __restrict__ targets,
            float* __restrict__ pred_out,
            float* __restrict__ out_scalar)
{
    __shared__ float s_ncm[NC*NC];
    __shared__ float s_log[NC*NC];
    for (int i = threadIdx.x; i < NC*NC; i += THREADS) {
        s_ncm[i] = g_ncm[i];
        s_log[i] = g_logncm[i];
    }
    __syncthreads();

    const int p  = blockIdx.x * THREADS + threadIdx.x;   // pixel index
    const int b  = p / HWS;
    const int hw = p - b * HWS;
    const float* lbase = logits   + (size_t)b * NC * HWS + hw;
    float*       pbase = pred_out + (size_t)b * NC * HWS + hw;

    // Issue all 19 loads up front (coalesced, MLP=19)
    float x[NC];
    #pragma unroll
    for (int c = 0; c < NC; c++)
        x[c] = __ldg(lbase + (size_t)c * HWS);
    const int t = targets[p];

    // Stable softmax over classes
    float m = x[0];
    #pragma unroll
    for (int c = 1; c < NC; c++) m = fmaxf(m, x[c]);
    float s = 0.f;
    #pragma unroll
    for (int c = 0; c < NC; c++) { x[c] = __expf(x[c] - m); s += x[c]; }
    const float inv = 1.f / s;

    // Single pass: store pred, accumulate ns = sum(w*p) and A = sum(w*p*(logw+log(p+eps)))
    float ns = 0.f, A = 0.f;
    #pragma unroll
    for (int c = 0; c < NC; c++) {
        const float pv = x[c] * inv;
        pbase[(size_t)c * HWS] = pv;
        const float e = s_ncm[c*NC + t] * pv;
        ns += e;
        A  += e * (s_log[c*NC + t] + __logf(pv + EPSF));
    }
    float loss = A / ns;

    // Deterministic block reduction
    #pragma unroll
    for (int off = 16; off > 0; off >>= 1)
        loss += __shfl_down_sync(0xffffffffu, loss, off);

    __shared__ float s_red[THREADS/32];
    __shared__ bool  s_last;
    if ((threadIdx.x & 31) == 0) s_red[threadIdx.x >> 5] = loss;
    __syncthreads();
    if (threadIdx.x == 0) {
        float v = 0.f;
        #pragma unroll
        for (int i = 0; i < THREADS/32; i++) v += s_red[i];
        g_partial[blockIdx.x] = v;
        __threadfence();
        unsigned int prev = atomicAdd(&g_count, 1u);
        s_last = (prev == NBLOCKS - 1);
    }
    __syncthreads();

    // Last block: deterministic final reduction over block partials
    if (s_last) {
        float sv = 0.f;
        for (int i = threadIdx.x; i < NBLOCKS; i += THREADS)
            sv += __ldcg(&g_partial[i]);                 // fixed per-thread order
        #pragma unroll
        for (int off = 16; off > 0; off >>= 1)
            sv += __shfl_down_sync(0xffffffffu, sv, off);
        if ((threadIdx.x & 31) == 0) s_red[threadIdx.x >> 5] = sv;
        __syncthreads();
        if (threadIdx.x == 0) {
            float v = 0.f;
            #pragma unroll
            for (int i = 0; i < THREADS/32; i++) v += s_red[i];
            out_scalar[0] = -v / (float)NPIX;
            g_count = 0;                                 // reset for graph replay
        }
    }
}

extern "C" void kernel_launch(void* const* d_in, const int* in_sizes, int n_in,
                              void* d_out, int out_size) {
    const float* logits  = (const float*)d_in[0];
    const int*   targets = (const int*)d_in[1];
    const float* cm      = (const float*)d_in[2];
    float* out = (float*)d_out;

    prep_kernel<<<1, NC*32>>>(cm);
    emloss_main<<<NBLOCKS, THREADS>>>(logits, targets, out, out + (out_size - 1));
}

// round 6
// speedup vs baseline: 1.1422x; 1.0531x over previous
#include <cuda_runtime.h>

#define NC 19
#define HWS (512*512)
#define NPIX (16*HWS)                 // 4,194,304 pixels
#define EPSF 1e-8f
#define THREADS 256
#define NBLOCKS (NPIX/THREADS)        // 16384

__device__ float g_ncmT[NC*NC];       // [t][c] transposed
__device__ float g_logncmT[NC*NC];    // [t][c] transposed
__device__ float g_partial[NBLOCKS];
__device__ unsigned int g_count;      // zero-initialized; self-resetting

// ---------------------------------------------------------------------------
// Prep: warp-per-row softmax of the 19x19 confusion matrix; stores transposed.
// ---------------------------------------------------------------------------
__global__ void prep_kernel(const float* __restrict__ cm) {
    const int w = threadIdx.x >> 5;       // row (class c)
    const int j = threadIdx.x & 31;       // col (target t)
    if (w >= NC) return;
    float v = (j < NC) ? cm[w*NC + j] : -1e30f;

    float m = v;
    #pragma unroll
    for (int off = 16; off > 0; off >>= 1)
        m = fmaxf(m, __shfl_xor_sync(0xffffffffu, m, off));

    float e = (j < NC) ? expf(v - m) : 0.f;
    float s = e;
    #pragma unroll
    for (int off = 16; off > 0; off >>= 1)
        s += __shfl_xor_sync(0xffffffffu, s, off);

    if (j < NC) {
        float pv = e / s;
        g_ncmT[j*NC + w]    = pv;              // transposed: [t][c]
        g_logncmT[j*NC + w] = logf(pv + EPSF);
    }
}

// ---------------------------------------------------------------------------
// Main: per-pixel softmax + EM loss + fused deterministic reduction.
// loss_pixel = A'/ns' - logS,  A' = sum_c w*e*(lw + t_c),  ns' = sum_c w*e
// (uses log(pv+eps) ~= log(pv) = t_c - logS; error << 1e-3 tolerance)
// ---------------------------------------------------------------------------
__global__ void __launch_bounds__(THREADS, 6)
emloss_main(const float* __restrict__ logits,
            const int*   __restrict__ targets,
            float* __restrict__ pred_out,
            float* __restrict__ out_scalar)
{
    __shared__ float s_ncmT[NC*NC];
    __shared__ float s_logT[NC*NC];
    for (int i = threadIdx.x; i < NC*NC; i += THREADS) {
        s_ncmT[i] = g_ncmT[i];
        s_logT[i] = g_logncmT[i];
    }
    __syncthreads();

    const int p  = blockIdx.x * THREADS + threadIdx.x;   // pixel index
    const int b  = p / HWS;
    const int hw = p - b * HWS;
    const float* lbase = logits   + (size_t)b * NC * HWS + hw;
    float*       pbase = pred_out + (size_t)b * NC * HWS + hw;

    const int t = targets[p];

    // Issue all 19 loads up front (coalesced, MLP=19)
    float x[NC];
    #pragma unroll
    for (int c = 0; c < NC; c++)
        x[c] = __ldg(lbase + (size_t)c * HWS);

    // Stable softmax max
    float m = x[0];
    #pragma unroll
    for (int c = 1; c < NC; c++) m = fmaxf(m, x[c]);

    // Fused exp + loss accumulation (single pass)
    const float* wrow = &s_ncmT[t*NC];
    const float* lrow = &s_logT[t*NC];
    float S = 0.f, ns = 0.f, A = 0.f;
    #pragma unroll
    for (int c = 0; c < NC; c++) {
        const float tc = x[c] - m;
        const float e  = __expf(tc);
        x[c] = e;
        S += e;
        const float we = wrow[c] * e;
        ns += we;
        A  += we * (lrow[c] + tc);
    }
    const float inv = 1.f / S;

    // Store pred
    #pragma unroll
    for (int c = 0; c < NC; c++)
        pbase[(size_t)c * HWS] = x[c] * inv;

    float loss = A / ns - __logf(S);

    // Deterministic block reduction
    #pragma unroll
    for (int off = 16; off > 0; off >>= 1)
        loss += __shfl_down_sync(0xffffffffu, loss, off);

    __shared__ float s_red[THREADS/32];
    __shared__ bool  s_last;
    if ((threadIdx.x & 31) == 0) s_red[threadIdx.x >> 5] = loss;
    __syncthreads();
    if (threadIdx.x == 0) {
        float v = 0.f;
        #pragma unroll
        for (int i = 0; i < THREADS/32; i++) v += s_red[i];
        g_partial[blockIdx.x] = v;
        __threadfence();
        unsigned int prev = atomicAdd(&g_count, 1u);
        s_last = (prev == NBLOCKS - 1);
    }
    __syncthreads();

    // Last block: deterministic final reduction over block partials
    if (s_last) {
        float sv = 0.f;
        for (int i = threadIdx.x; i < NBLOCKS; i += THREADS)
            sv += __ldcg(&g_partial[i]);                 // fixed per-thread order
        #pragma unroll
        for (int off = 16; off > 0; off >>= 1)
            sv += __shfl_down_sync(0xffffffffu, sv, off);
        if ((threadIdx.x & 31) == 0) s_red[threadIdx.x >> 5] = sv;
        __syncthreads();
        if (threadIdx.x == 0) {
            float v = 0.f;
            #pragma unroll
            for (int i = 0; i < THREADS/32; i++) v += s_red[i];
            out_scalar[0] = -v / (float)NPIX;
            g_count = 0;                                 // reset for graph replay
        }
    }
}

extern "C" void kernel_launch(void* const* d_in, const int* in_sizes, int n_in,
                              void* d_out, int out_size) {
    const float* logits  = (const float*)d_in[0];
    const int*   targets = (const int*)d_in[1];
    const float* cm      = (const float*)d_in[2];
    float* out = (float*)d_out;

    prep_kernel<<<1, NC*32>>>(cm);
    emloss_main<<<NBLOCKS, THREADS>>>(logits, targets, out, out + (out_size - 1));
}